// round 14
// baseline (speedup 1.0000x reference)
#include <cuda_runtime.h>

#define D_MODEL 128
#define C_FEAT  16
#define LN_EPS  1e-5f
#define ROWS_PER_BLOCK 128
#define ROWS_PER_WARP  16

typedef unsigned long long ull;

// Packed per-node xy for both batches: {x_b0, y_b0, x_b1, y_b1}.
// 50000 nodes * 16B = 800KB -> fully L2-resident gather table.
#define N_NODES 50000
__device__ float4 g_xy[N_NODES];

// Runtime-detected index dtype: 1 if edge_index buffer is int32, 0 if int64.
__device__ int g_is32;

// ---------------------------------------------------------------------------
// f32x2 packed-math helpers (sm_103a FFMA2/FADD2/FMUL2 via PTX .f32x2).
// ---------------------------------------------------------------------------
__device__ __forceinline__ ull splat2(float f) {
    ull r; asm("mov.b64 %0, {%1, %1};" : "=l"(r) : "f"(f)); return r;
}
__device__ __forceinline__ ull pack2(float a, float b) {
    ull r; asm("mov.b64 %0, {%1, %2};" : "=l"(r) : "f"(a), "f"(b)); return r;
}
__device__ __forceinline__ void unpack2(ull v, float& a, float& b) {
    asm("mov.b64 {%0, %1}, %2;" : "=f"(a), "=f"(b) : "l"(v));
}
__device__ __forceinline__ ull fma2(ull a, ull b, ull c) {
    ull d; asm("fma.rn.f32x2 %0, %1, %2, %3;" : "=l"(d) : "l"(a), "l"(b), "l"(c));
    return d;
}
__device__ __forceinline__ ull mul2(ull a, ull b) {
    ull d; asm("mul.rn.f32x2 %0, %1, %2;" : "=l"(d) : "l"(a), "l"(b)); return d;
}
__device__ __forceinline__ ull add2(ull a, ull b) {
    ull d; asm("add.rn.f32x2 %0, %1, %2;" : "=l"(d) : "l"(a), "l"(b)); return d;
}
__device__ __forceinline__ float frcp(float x) {
    float r; asm("rcp.approx.f32 %0, %1;" : "=f"(r) : "f"(x)); return r;
}
__device__ __forceinline__ float fex2(float x) {
    float r; asm("ex2.approx.f32 %0, %1;" : "=f"(r) : "f"(x)); return r;
}

// ---------------------------------------------------------------------------
// Packed GELU on a pair. erf via Abramowitz-Stegun 7.1.26 (|err|<=1.5e-7):
//   gelu(x) = 0.5 x + 0.5|x| (1 - poly(k) e^{-t^2}),  t=|x|/sqrt2
// All poly/affine math in f32x2 (FFMA2); only rcp/ex2 are scalar MUFU.
// ---------------------------------------------------------------------------
struct GeluConsts {
    ull invs2, p, one, a5, a4, a3, a2, a1, half, nl2e;
};
__device__ __forceinline__ ull gelu2(ull x2, const GeluConsts& C) {
    ull ax2 = x2 & 0x7FFFFFFF7FFFFFFFULL;
    ull t2  = mul2(ax2, C.invs2);
    ull q2  = fma2(C.p, t2, C.one);
    float qa, qb; unpack2(q2, qa, qb);
    ull k2  = pack2(frcp(qa), frcp(qb));
    ull p2  = fma2(C.a5, k2, C.a4);
    p2 = fma2(p2, k2, C.a3);
    p2 = fma2(p2, k2, C.a2);
    p2 = fma2(p2, k2, C.a1);
    p2 = mul2(p2, k2);
    ull m2 = mul2(mul2(t2, t2), C.nl2e);      // -t^2 * log2(e)
    float ma, mb; unpack2(m2, ma, mb);
    ull e2 = pack2(fex2(ma), fex2(mb));
    ull np2 = p2 ^ 0x8000000080000000ULL;
    ull erf2 = fma2(np2, e2, C.one);          // 1 - p*e
    ull hax2 = mul2(ax2, C.half);
    ull hx2  = mul2(x2,  C.half);
    return fma2(hax2, erf2, hx2);
}

// ---------------------------------------------------------------------------
// Encoder kernel with embedded xy_pack/detector role blocks.
// Grid layout: [0, nxy) = xy-pack role; nxy = detector; (nxy, nxy+nenc] =
// encoder blocks. The xy/detector blocks finish inside the encoder's first
// wave, and the kernel boundary before edge_kernel guarantees completion —
// the separate 5.3us xy_pack launch disappears into encoder slack.
//
// Encoder role: register-resident packed weights (f32x2); each lane owns 4
// consecutive channels as 2 packed pairs. GEMM uses TWO independent
// accumulator chains per pair (8-deep instead of 16-deep FFMA2 chain) to cut
// per-row serial latency at low warp count.
// ---------------------------------------------------------------------------
__global__ void __launch_bounds__(256, 2) encoder_kernel(
        const float* __restrict__ x,
        const int*   __restrict__ ei32,
        const float* __restrict__ W,
        const float* __restrict__ bias,
        const float* __restrict__ gamma,
        const float* __restrict__ beta,
        float* __restrict__ out,
        int rows, int n_nodes, int nxy) {
    int bid = blockIdx.x;
    if (bid < nxy) {                              // xy-pack role
        int r = bid * blockDim.x + threadIdx.x;
        if (r < rows) {
            float2 xy = __ldg(reinterpret_cast<const float2*>(
                x + (size_t)r * C_FEAT));
            int b = (r >= n_nodes) ? 1 : 0;
            int n = r - b * n_nodes;
            if (n >= 0 && n < N_NODES) {
                float2* p = reinterpret_cast<float2*>(
                    reinterpret_cast<char*>(&g_xy[n]) + (size_t)b * 8);
                *p = xy;
            }
        }
        return;
    }
    if (bid == nxy) {                             // detector role
        if (threadIdx.x < 32) {
            int f = 0;
#pragma unroll
            for (int i = 0; i < 8; i++)
                f |= __ldg(ei32 + ((threadIdx.x * 8 + i) * 2 + 1));
            unsigned any = __ballot_sync(0xFFFFFFFFu, f != 0);
            if (threadIdx.x == 0) g_is32 = (any != 0) ? 1 : 0;
        }
        return;
    }

    // ---- encoder role ----
    __shared__ float sRow[ROWS_PER_BLOCK * C_FEAT];   // 8KB: 128 rows staged

    int base = (bid - nxy - 1) * ROWS_PER_BLOCK;
    {   // coalesced staging of this block's rows
        int gbase = base * C_FEAT;
        int total = rows * C_FEAT;
#pragma unroll
        for (int i = 0; i < ROWS_PER_BLOCK * C_FEAT / 256; i++) {
            int li = threadIdx.x + i * 256;
            int gi = gbase + li;
            sRow[li] = (gi < total) ? x[gi] : 0.f;
        }
    }

    int warp = threadIdx.x >> 5;
    int lane = threadIdx.x & 31;

    // Packed register-resident weights for channels 4*lane..4*lane+3.
    ull wA[C_FEAT], wB[C_FEAT];
#pragma unroll
    for (int c = 0; c < C_FEAT; c++) {
        float4 wf = __ldg(reinterpret_cast<const float4*>(W + c * D_MODEL) + lane);
        wA[c] = pack2(wf.x, wf.y);
        wB[c] = pack2(wf.z, wf.w);
    }
    float4 bf = __ldg(reinterpret_cast<const float4*>(bias)  + lane);
    float4 gf = __ldg(reinterpret_cast<const float4*>(gamma) + lane);
    float4 ef = __ldg(reinterpret_cast<const float4*>(beta)  + lane);
    ull b2a = pack2(bf.x, bf.y), b2b = pack2(bf.z, bf.w);
    ull g2a = pack2(gf.x, gf.y), g2b = pack2(gf.z, gf.w);
    ull e2a = pack2(ef.x, ef.y), e2b = pack2(ef.z, ef.w);

    GeluConsts C;
    C.invs2 = splat2(0.70710678118654752f);
    C.p     = splat2(0.3275911f);
    C.one   = splat2(1.0f);
    C.a5    = splat2(1.061405429f);
    C.a4    = splat2(-1.453152027f);
    C.a3    = splat2(1.421413741f);
    C.a2    = splat2(-0.284496736f);
    C.a1    = splat2(0.254829592f);
    C.half  = splat2(0.5f);
    C.nl2e  = splat2(-1.4426950408889634f);   // -log2(e)

    __syncthreads();

    int rbase = base + warp * ROWS_PER_WARP;
#pragma unroll 2
    for (int t = 0; t < ROWS_PER_WARP; t++) {
        int r = rbase + t;
        if (r >= rows) break;

        const float4* srow4 = reinterpret_cast<const float4*>(
            sRow + (warp * ROWS_PER_WARP + t) * C_FEAT);
        float4 f0 = srow4[0], f1 = srow4[1], f2 = srow4[2], f3 = srow4[3];
        float sv[C_FEAT] = {f0.x, f0.y, f0.z, f0.w, f1.x, f1.y, f1.z, f1.w,
                            f2.x, f2.y, f2.z, f2.w, f3.x, f3.y, f3.z, f3.w};

        // GEMM with two independent chains per packed pair (8-deep each).
        ull acc0 = b2a, acc1 = b2b;
        ull alt0 = splat2(0.f), alt1 = splat2(0.f);
#pragma unroll
        for (int c = 0; c < C_FEAT; c += 2) {
            ull s2a = splat2(sv[c]);
            ull s2b = splat2(sv[c + 1]);
            acc0 = fma2(s2a, wA[c], acc0);
            acc1 = fma2(s2a, wB[c], acc1);
            alt0 = fma2(s2b, wA[c + 1], alt0);
            alt1 = fma2(s2b, wB[c + 1], alt1);
        }
        acc0 = add2(acc0, alt0);
        acc1 = add2(acc1, alt1);

        ull v0 = gelu2(acc0, C);
        ull v1 = gelu2(acc1, C);

        // LN statistics: red = {sum, sumsq} packed, 5-level butterfly.
        ull sp = add2(v0, v1);
        ull sq = mul2(v0, v0);
        sq = fma2(v1, v1, sq);
        float spa, spb, sqa, sqb;
        unpack2(sp, spa, spb); unpack2(sq, sqa, sqb);
        ull red = pack2(spa + spb, sqa + sqb);
#pragma unroll
        for (int o = 16; o > 0; o >>= 1) {
            double sh = __shfl_xor_sync(0xFFFFFFFFu,
                        __longlong_as_double((long long)red), o);
            red = add2(red, (ull)__double_as_longlong(sh));
        }
        float sum, sumsq; unpack2(red, sum, sumsq);
        float mean = sum * (1.0f / D_MODEL);
        float var  = sumsq * (1.0f / D_MODEL) - mean * mean;
        float rstd = rsqrtf(var + LN_EPS);
        ull nmean2 = splat2(-mean);
        ull rstd2  = splat2(rstd);

        // Normalize + affine (packed): out = (v - mean)*rstd*gamma + beta
        ull o0 = fma2(mul2(add2(v0, nmean2), rstd2), g2a, e2a);
        ull o1 = fma2(mul2(add2(v1, nmean2), rstd2), g2b, e2b);

        float4 o4;
        unpack2(o0, o4.x, o4.y);
        unpack2(o1, o4.z, o4.w);
        reinterpret_cast<float4*>(out + (size_t)r * D_MODEL)[lane] = o4;
    }
}

// ---------------------------------------------------------------------------
// Edge deterrence: one thread handles FOUR consecutive edges, BOTH batches.
//   det[b*E + e] = -0.5 * || xy[b*N + src[e]] - xy[b*N + dst[e]] ||^2
// Both batches' coords packed in one float4 -> 2 gathers per edge. Index
// dtype chosen at runtime via g_is32 (uniform branch). Indices clamped to
// [0, n_nodes) so a bad assumption yields rel_err, never an illegal access.
// ---------------------------------------------------------------------------
__global__ void __launch_bounds__(256) edge_kernel(
        const void* __restrict__ ei_raw,
        float* __restrict__ det, int E, int n_nodes) {
    int q = blockIdx.x * blockDim.x + threadIdx.x;
    int e = q * 4;
    if (e >= E) return;

    unsigned s[4], d[4];
    bool full = (e + 3 < E);
    if (full) {
        if (g_is32) {
            const int* p = (const int*)ei_raw;
            int4 a = __ldg(reinterpret_cast<const int4*>(p + e));
            int4 b = __ldg(reinterpret_cast<const int4*>(p + (size_t)E + e));
            s[0] = a.x; s[1] = a.y; s[2] = a.z; s[3] = a.w;
            d[0] = b.x; d[1] = b.y; d[2] = b.z; d[3] = b.w;
        } else {
            const long long* p = (const long long*)ei_raw;
            longlong2 a0 = __ldg(reinterpret_cast<const longlong2*>(p + e));
            longlong2 a1 = __ldg(reinterpret_cast<const longlong2*>(p + e + 2));
            longlong2 b0 = __ldg(reinterpret_cast<const longlong2*>(p + (size_t)E + e));
            longlong2 b1 = __ldg(reinterpret_cast<const longlong2*>(p + (size_t)E + e + 2));
            s[0] = (unsigned)a0.x; s[1] = (unsigned)a0.y;
            s[2] = (unsigned)a1.x; s[3] = (unsigned)a1.y;
            d[0] = (unsigned)b0.x; d[1] = (unsigned)b0.y;
            d[2] = (unsigned)b1.x; d[3] = (unsigned)b1.y;
        }
    } else {
#pragma unroll
        for (int k = 0; k < 4; k++) {
            if (e + k < E) {
                if (g_is32) {
                    const int* p = (const int*)ei_raw;
                    s[k] = (unsigned)__ldg(p + e + k);
                    d[k] = (unsigned)__ldg(p + (size_t)E + e + k);
                } else {
                    const long long* p = (const long long*)ei_raw;
                    s[k] = (unsigned)__ldg(p + e + k);
                    d[k] = (unsigned)__ldg(p + (size_t)E + e + k);
                }
            } else { s[k] = 0; d[k] = 0; }
        }
    }

    unsigned lim = (unsigned)(n_nodes - 1);
    float4 ps[4], pd[4];
#pragma unroll
    for (int k = 0; k < 4; k++) {
        ps[k] = __ldg(&g_xy[min(s[k], lim)]);
        pd[k] = __ldg(&g_xy[min(d[k], lim)]);
    }

    float r0[4], r1[4];
#pragma unroll
    for (int k = 0; k < 4; k++) {
        float dx0 = ps[k].x - pd[k].x, dy0 = ps[k].y - pd[k].y;
        float dx1 = ps[k].z - pd[k].z, dy1 = ps[k].w - pd[k].w;
        r0[k] = -0.5f * (dx0 * dx0 + dy0 * dy0);
        r1[k] = -0.5f * (dx1 * dx1 + dy1 * dy1);
    }

    if (full) {
        *reinterpret_cast<float4*>(det + e) =
            make_float4(r0[0], r0[1], r0[2], r0[3]);
        *reinterpret_cast<float4*>(det + (size_t)E + e) =
            make_float4(r1[0], r1[1], r1[2], r1[3]);
    } else {
#pragma unroll
        for (int k = 0; k < 4; k++) {
            if (e + k < E) {
                det[e + k] = r0[k];
                det[(size_t)E + e + k] = r1[k];
            }
        }
    }
}

// ---------------------------------------------------------------------------
// Launch. Inputs (metadata order): static, edge_index, fc_w, fc_b, ln_g, ln_b
// Output: [H0 flat (rows*128 f32)] ++ [det flat (2*E f32)]
// E derived from out_size: out_size = rows*128 + 2*E. Two launches total:
// encoder (with embedded xy/detector role blocks) then edge. Single stream,
// no statics — fully graph-capturable.
// ---------------------------------------------------------------------------
extern "C" void kernel_launch(void* const* d_in, const int* in_sizes, int n_in,
                              void* d_out, int out_size) {
    const float* x    = (const float*)d_in[0];
    const void*  ei   = d_in[1];
    const float* W    = (const float*)d_in[2];
    const float* bias = (const float*)d_in[3];
    const float* g    = (const float*)d_in[4];
    const float* be   = (const float*)d_in[5];

    int rows    = in_sizes[0] / C_FEAT;                    // B*N = 100000
    int n_nodes = rows / 2;                                // N = 50000 (B=2)
    long long detN = (long long)out_size - (long long)rows * D_MODEL; // B*E
    int E = (int)(detN / 2);                               // 1600000

    float* H0  = (float*)d_out;
    float* det = (float*)d_out + (size_t)rows * D_MODEL;

    // 1) encoder + embedded xy-pack/detector roles.
    int nxy  = (rows + 255) / 256;                          // 391
    int nenc = (rows + ROWS_PER_BLOCK - 1) / ROWS_PER_BLOCK; // 782
    encoder_kernel<<<nxy + 1 + nenc, 256>>>(x, (const int*)ei, W, bias, g, be,
                                            H0, rows, n_nodes, nxy);

    // 2) edge deterrence, 4 edges per thread.
    int nquad = (E + 3) / 4;
    edge_kernel<<<(nquad + 255) / 256, 256>>>(ei, det, E, n_nodes);
}

// round 17
// speedup vs baseline: 1.0854x; 1.0854x over previous
#include <cuda_runtime.h>

#define D_MODEL 128
#define C_FEAT  16
#define LN_EPS  1e-5f
#define ROWS_PER_BLOCK 128
#define ROWS_PER_WARP  16

typedef unsigned long long ull;

// Packed per-node xy for both batches: {x_b0, y_b0, x_b1, y_b1}.
// 50000 nodes * 16B = 800KB -> fully L2-resident gather table.
#define N_NODES 50000
__device__ float4 g_xy[N_NODES];

// Runtime-detected index dtype: 1 if edge_index buffer is int32, 0 if int64.
__device__ int g_is32;

// ---------------------------------------------------------------------------
// f32x2 packed-math helpers (sm_103a FFMA2/FADD2/FMUL2 via PTX .f32x2).
// ---------------------------------------------------------------------------
__device__ __forceinline__ ull splat2(float f) {
    ull r; asm("mov.b64 %0, {%1, %1};" : "=l"(r) : "f"(f)); return r;
}
__device__ __forceinline__ ull pack2(float a, float b) {
    ull r; asm("mov.b64 %0, {%1, %2};" : "=l"(r) : "f"(a), "f"(b)); return r;
}
__device__ __forceinline__ void unpack2(ull v, float& a, float& b) {
    asm("mov.b64 {%0, %1}, %2;" : "=f"(a), "=f"(b) : "l"(v));
}
__device__ __forceinline__ ull fma2(ull a, ull b, ull c) {
    ull d; asm("fma.rn.f32x2 %0, %1, %2, %3;" : "=l"(d) : "l"(a), "l"(b), "l"(c));
    return d;
}
__device__ __forceinline__ ull mul2(ull a, ull b) {
    ull d; asm("mul.rn.f32x2 %0, %1, %2;" : "=l"(d) : "l"(a), "l"(b)); return d;
}
__device__ __forceinline__ ull add2(ull a, ull b) {
    ull d; asm("add.rn.f32x2 %0, %1, %2;" : "=l"(d) : "l"(a), "l"(b)); return d;
}
__device__ __forceinline__ float frcp(float x) {
    float r; asm("rcp.approx.f32 %0, %1;" : "=f"(r) : "f"(x)); return r;
}
__device__ __forceinline__ float fex2(float x) {
    float r; asm("ex2.approx.f32 %0, %1;" : "=f"(r) : "f"(x)); return r;
}

// ---------------------------------------------------------------------------
// Packed GELU on a pair. erf via Abramowitz-Stegun 7.1.26 (|err|<=1.5e-7):
//   gelu(x) = 0.5 x + 0.5|x| (1 - poly(k) e^{-t^2}),  t=|x|/sqrt2
// All poly/affine math in f32x2 (FFMA2); only rcp/ex2 are scalar MUFU.
// ---------------------------------------------------------------------------
struct GeluConsts {
    ull invs2, p, one, a5, a4, a3, a2, a1, half, nl2e;
};
__device__ __forceinline__ ull gelu2(ull x2, const GeluConsts& C) {
    ull ax2 = x2 & 0x7FFFFFFF7FFFFFFFULL;
    ull t2  = mul2(ax2, C.invs2);
    ull q2  = fma2(C.p, t2, C.one);
    float qa, qb; unpack2(q2, qa, qb);
    ull k2  = pack2(frcp(qa), frcp(qb));
    ull p2  = fma2(C.a5, k2, C.a4);
    p2 = fma2(p2, k2, C.a3);
    p2 = fma2(p2, k2, C.a2);
    p2 = fma2(p2, k2, C.a1);
    p2 = mul2(p2, k2);
    ull m2 = mul2(mul2(t2, t2), C.nl2e);      // -t^2 * log2(e)
    float ma, mb; unpack2(m2, ma, mb);
    ull e2 = pack2(fex2(ma), fex2(mb));
    ull np2 = p2 ^ 0x8000000080000000ULL;
    ull erf2 = fma2(np2, e2, C.one);          // 1 - p*e
    ull hax2 = mul2(ax2, C.half);
    ull hx2  = mul2(x2,  C.half);
    return fma2(hax2, erf2, hx2);
}

// ---------------------------------------------------------------------------
// Encoder (f32x2, row-paired). Each lane owns 4 consecutive channels as 2
// packed pairs; W[:, 4l..4l+3] in 32 ull regs. Rows processed in PAIRS:
// GEMM+GELU for both, then both rows' LN butterflies run interleaved so the
// two independent 5-level shuffle chains pipeline (~170 cyc covers 2 rows
// instead of ~300 serial). Lane 0 stashes each row's (x,y) into g_xy as a
// side effect (zero-cost; data is already in smem). LAST block = dtype
// detector: genuine int64 indices < 50000 have all-zero high words.
// ---------------------------------------------------------------------------
__global__ void __launch_bounds__(256, 2) encoder_kernel(
        const float* __restrict__ x,
        const int*   __restrict__ ei32,
        const float* __restrict__ W,
        const float* __restrict__ bias,
        const float* __restrict__ gamma,
        const float* __restrict__ beta,
        float* __restrict__ out,
        int rows, int n_nodes) {
    if (blockIdx.x == gridDim.x - 1) {            // detector block
        if (threadIdx.x < 32) {
            int f = 0;
#pragma unroll
            for (int i = 0; i < 8; i++)
                f |= __ldg(ei32 + ((threadIdx.x * 8 + i) * 2 + 1));
            unsigned any = __ballot_sync(0xFFFFFFFFu, f != 0);
            if (threadIdx.x == 0) g_is32 = (any != 0) ? 1 : 0;
        }
        return;
    }

    __shared__ float sRow[ROWS_PER_BLOCK * C_FEAT];   // 8KB: 128 rows staged

    int base = blockIdx.x * ROWS_PER_BLOCK;
    {   // coalesced staging of this block's rows
        int gbase = base * C_FEAT;
        int total = rows * C_FEAT;
#pragma unroll
        for (int i = 0; i < ROWS_PER_BLOCK * C_FEAT / 256; i++) {
            int li = threadIdx.x + i * 256;
            int gi = gbase + li;
            sRow[li] = (gi < total) ? x[gi] : 0.f;
        }
    }

    int warp = threadIdx.x >> 5;
    int lane = threadIdx.x & 31;

    // Packed register-resident weights for channels 4*lane..4*lane+3.
    ull wA[C_FEAT], wB[C_FEAT];
#pragma unroll
    for (int c = 0; c < C_FEAT; c++) {
        float4 wf = __ldg(reinterpret_cast<const float4*>(W + c * D_MODEL) + lane);
        wA[c] = pack2(wf.x, wf.y);
        wB[c] = pack2(wf.z, wf.w);
    }
    float4 bf = __ldg(reinterpret_cast<const float4*>(bias)  + lane);
    float4 gf = __ldg(reinterpret_cast<const float4*>(gamma) + lane);
    float4 ef = __ldg(reinterpret_cast<const float4*>(beta)  + lane);
    ull b2a = pack2(bf.x, bf.y), b2b = pack2(bf.z, bf.w);
    ull g2a = pack2(gf.x, gf.y), g2b = pack2(gf.z, gf.w);
    ull e2a = pack2(ef.x, ef.y), e2b = pack2(ef.z, ef.w);

    GeluConsts C;
    C.invs2 = splat2(0.70710678118654752f);
    C.p     = splat2(0.3275911f);
    C.one   = splat2(1.0f);
    C.a5    = splat2(1.061405429f);
    C.a4    = splat2(-1.453152027f);
    C.a3    = splat2(1.421413741f);
    C.a2    = splat2(-0.284496736f);
    C.a1    = splat2(0.254829592f);
    C.half  = splat2(0.5f);
    C.nl2e  = splat2(-1.4426950408889634f);   // -log2(e)

    __syncthreads();

    int rbase = base + warp * ROWS_PER_WARP;
#pragma unroll 1
    for (int tp = 0; tp < ROWS_PER_WARP; tp += 2) {
        int r0 = rbase + tp;
        if (r0 >= rows) break;
        int r1 = r0 + 1;
        bool has1 = (r1 < rows);

        const float* s0 = sRow + (warp * ROWS_PER_WARP + tp) * C_FEAT;
        const float* s1 = s0 + C_FEAT;            // smem zero-filled at tail

        // Stash packed xy for the edge kernel (lane 0; data already staged).
        if (lane == 0) {
            int b0 = (r0 >= n_nodes) ? 1 : 0;
            int n0 = r0 - b0 * n_nodes;
            reinterpret_cast<float2*>(
                reinterpret_cast<char*>(&g_xy[n0]) + (size_t)b0 * 8)[0] =
                make_float2(s0[0], s0[1]);
            if (has1) {
                int b1 = (r1 >= n_nodes) ? 1 : 0;
                int n1 = r1 - b1 * n_nodes;
                reinterpret_cast<float2*>(
                    reinterpret_cast<char*>(&g_xy[n1]) + (size_t)b1 * 8)[0] =
                    make_float2(s1[0], s1[1]);
            }
        }

        // GEMM both rows: 4 independent FFMA2 chains (2 rows x 2 pairs).
        ull aA0 = b2a, aB0 = b2b, aA1 = b2a, aB1 = b2b;
#pragma unroll
        for (int c = 0; c < C_FEAT; c++) {
            ull sc0 = splat2(s0[c]);
            ull sc1 = splat2(s1[c]);
            aA0 = fma2(sc0, wA[c], aA0);
            aB0 = fma2(sc0, wB[c], aB0);
            aA1 = fma2(sc1, wA[c], aA1);
            aB1 = fma2(sc1, wB[c], aB1);
        }

        ull vA0 = gelu2(aA0, C), vB0 = gelu2(aB0, C);
        ull vA1 = gelu2(aA1, C), vB1 = gelu2(aB1, C);

        // Per-row packed stats {sum, sumsq}.
        ull sp0 = add2(vA0, vB0);
        ull sq0 = fma2(vB0, vB0, mul2(vA0, vA0));
        ull sp1 = add2(vA1, vB1);
        ull sq1 = fma2(vB1, vB1, mul2(vA1, vA1));
        float a, b, c2, d2;
        unpack2(sp0, a, b); unpack2(sq0, c2, d2);
        ull red0 = pack2(a + b, c2 + d2);
        unpack2(sp1, a, b); unpack2(sq1, c2, d2);
        ull red1 = pack2(a + b, c2 + d2);

        // Interleaved butterflies: two independent chains pipeline.
#pragma unroll
        for (int o = 16; o > 0; o >>= 1) {
            double h0 = __shfl_xor_sync(0xFFFFFFFFu,
                        __longlong_as_double((long long)red0), o);
            double h1 = __shfl_xor_sync(0xFFFFFFFFu,
                        __longlong_as_double((long long)red1), o);
            red0 = add2(red0, (ull)__double_as_longlong(h0));
            red1 = add2(red1, (ull)__double_as_longlong(h1));
        }

        // Row 0 normalize + store.
        {
            float sum, sumsq; unpack2(red0, sum, sumsq);
            float mean = sum * (1.0f / D_MODEL);
            float var  = sumsq * (1.0f / D_MODEL) - mean * mean;
            float rstd = rsqrtf(var + LN_EPS);
            ull nm = splat2(-mean), rs = splat2(rstd);
            ull o0 = fma2(mul2(add2(vA0, nm), rs), g2a, e2a);
            ull o1 = fma2(mul2(add2(vB0, nm), rs), g2b, e2b);
            float4 o4;
            unpack2(o0, o4.x, o4.y); unpack2(o1, o4.z, o4.w);
            reinterpret_cast<float4*>(out + (size_t)r0 * D_MODEL)[lane] = o4;
        }
        // Row 1 normalize + store.
        if (has1) {
            float sum, sumsq; unpack2(red1, sum, sumsq);
            float mean = sum * (1.0f / D_MODEL);
            float var  = sumsq * (1.0f / D_MODEL) - mean * mean;
            float rstd = rsqrtf(var + LN_EPS);
            ull nm = splat2(-mean), rs = splat2(rstd);
            ull o0 = fma2(mul2(add2(vA1, nm), rs), g2a, e2a);
            ull o1 = fma2(mul2(add2(vB1, nm), rs), g2b, e2b);
            float4 o4;
            unpack2(o0, o4.x, o4.y); unpack2(o1, o4.z, o4.w);
            reinterpret_cast<float4*>(out + (size_t)r1 * D_MODEL)[lane] = o4;
        }
    }
}

// ---------------------------------------------------------------------------
// Edge deterrence: one thread handles FOUR consecutive edges, BOTH batches.
//   det[b*E + e] = -0.5 * || xy[b*N + src[e]] - xy[b*N + dst[e]] ||^2
// Both batches' coords packed in one float4 -> 2 gathers per edge. Index
// dtype chosen at runtime via g_is32 (uniform branch). Indices clamped to
// [0, n_nodes) so a bad assumption yields rel_err, never an illegal access.
// ---------------------------------------------------------------------------
__global__ void __launch_bounds__(256) edge_kernel(
        const void* __restrict__ ei_raw,
        float* __restrict__ det, int E, int n_nodes) {
    int q = blockIdx.x * blockDim.x + threadIdx.x;
    int e = q * 4;
    if (e >= E) return;

    unsigned s[4], d[4];
    bool full = (e + 3 < E);
    if (full) {
        if (g_is32) {
            const int* p = (const int*)ei_raw;
            int4 a = __ldg(reinterpret_cast<const int4*>(p + e));
            int4 b = __ldg(reinterpret_cast<const int4*>(p + (size_t)E + e));
            s[0] = a.x; s[1] = a.y; s[2] = a.z; s[3] = a.w;
            d[0] = b.x; d[1] = b.y; d[2] = b.z; d[3] = b.w;
        } else {
            const long long* p = (const long long*)ei_raw;
            longlong2 a0 = __ldg(reinterpret_cast<const longlong2*>(p + e));
            longlong2 a1 = __ldg(reinterpret_cast<const longlong2*>(p + e + 2));
            longlong2 b0 = __ldg(reinterpret_cast<const longlong2*>(p + (size_t)E + e));
            longlong2 b1 = __ldg(reinterpret_cast<const longlong2*>(p + (size_t)E + e + 2));
            s[0] = (unsigned)a0.x; s[1] = (unsigned)a0.y;
            s[2] = (unsigned)a1.x; s[3] = (unsigned)a1.y;
            d[0] = (unsigned)b0.x; d[1] = (unsigned)b0.y;
            d[2] = (unsigned)b1.x; d[3] = (unsigned)b1.y;
        }
    } else {
#pragma unroll
        for (int k = 0; k < 4; k++) {
            if (e + k < E) {
                if (g_is32) {
                    const int* p = (const int*)ei_raw;
                    s[k] = (unsigned)__ldg(p + e + k);
                    d[k] = (unsigned)__ldg(p + (size_t)E + e + k);
                } else {
                    const long long* p = (const long long*)ei_raw;
                    s[k] = (unsigned)__ldg(p + e + k);
                    d[k] = (unsigned)__ldg(p + (size_t)E + e + k);
                }
            } else { s[k] = 0; d[k] = 0; }
        }
    }

    unsigned lim = (unsigned)(n_nodes - 1);
    float4 ps[4], pd[4];
#pragma unroll
    for (int k = 0; k < 4; k++) {
        ps[k] = __ldg(&g_xy[min(s[k], lim)]);
        pd[k] = __ldg(&g_xy[min(d[k], lim)]);
    }

    float r0[4], r1[4];
#pragma unroll
    for (int k = 0; k < 4; k++) {
        float dx0 = ps[k].x - pd[k].x, dy0 = ps[k].y - pd[k].y;
        float dx1 = ps[k].z - pd[k].z, dy1 = ps[k].w - pd[k].w;
        r0[k] = -0.5f * (dx0 * dx0 + dy0 * dy0);
        r1[k] = -0.5f * (dx1 * dx1 + dy1 * dy1);
    }

    if (full) {
        *reinterpret_cast<float4*>(det + e) =
            make_float4(r0[0], r0[1], r0[2], r0[3]);
        *reinterpret_cast<float4*>(det + (size_t)E + e) =
            make_float4(r1[0], r1[1], r1[2], r1[3]);
    } else {
#pragma unroll
        for (int k = 0; k < 4; k++) {
            if (e + k < E) {
                det[e + k] = r0[k];
                det[(size_t)E + e + k] = r1[k];
            }
        }
    }
}

// ---------------------------------------------------------------------------
// Launch. Inputs (metadata order): static, edge_index, fc_w, fc_b, ln_g, ln_b
// Output: [H0 flat (rows*128 f32)] ++ [det flat (2*E f32)]
// E derived from out_size: out_size = rows*128 + 2*E. Two launches: encoder
// (with in-loop xy stash + detector block) then edge. Single stream, no
// statics — fully graph-capturable.
// ---------------------------------------------------------------------------
extern "C" void kernel_launch(void* const* d_in, const int* in_sizes, int n_in,
                              void* d_out, int out_size) {
    const float* x    = (const float*)d_in[0];
    const void*  ei   = d_in[1];
    const float* W    = (const float*)d_in[2];
    const float* bias = (const float*)d_in[3];
    const float* g    = (const float*)d_in[4];
    const float* be   = (const float*)d_in[5];

    int rows    = in_sizes[0] / C_FEAT;                    // B*N = 100000
    int n_nodes = rows / 2;                                // N = 50000 (B=2)
    long long detN = (long long)out_size - (long long)rows * D_MODEL; // B*E
    int E = (int)(detN / 2);                               // 1600000

    float* H0  = (float*)d_out;
    float* det = (float*)d_out + (size_t)rows * D_MODEL;

    // 1) encoder (+1 detector block; xy stash inside the row loop).
    int nenc = (rows + ROWS_PER_BLOCK - 1) / ROWS_PER_BLOCK;   // 782
    encoder_kernel<<<nenc + 1, 256>>>(x, (const int*)ei, W, bias, g, be,
                                      H0, rows, n_nodes);

    // 2) edge deterrence, 4 edges per thread.
    int nquad = (E + 3) / 4;
    edge_kernel<<<(nquad + 255) / 256, 256>>>(ei, det, E, n_nodes);
}